// round 14
// baseline (speedup 1.0000x reference)
#include <cuda_runtime.h>
#include <cuda_bf16.h>
#include <cstdint>

#define N_SRC  100000
#define N_DST  50000
#define E_CNT  600000
#define D      128          // D_IN == D_OUT == 128

#define BKT    64           // bucket capacity per dst (Poisson(12): P(deg>64) ~ 1e-38)

#define FILL_NB ((E_CNT / 4 + 255) / 256)                    // 586
#define WSP_NB  ((D * D + 255) / 256)                        // 64

#define TILE_M 128
#define GRID_N ((N_DST + TILE_M - 1) / TILE_M)               // 391

// padded row stride for smem tiles (bf16 elements)
#define LDA 136

// ---------------- device scratch (no allocation allowed) ----------------
__device__ int   g_deg[N_DST];
__device__ int   g_edges[(size_t)N_DST * BKT];   // 12.8 MB padded buckets
// W split into bf16 hi/lo, stored as B[n][k] (= W[k][n]) row-major, k contiguous
__device__ __nv_bfloat16 g_Whi[D * D];
__device__ __nv_bfloat16 g_Wlo[D * D];

// ---------------- helpers ----------------
__device__ __forceinline__ uint32_t smem_u32(const void* p) {
    uint32_t a;
    asm("{ .reg .u64 t; cvta.to.shared.u64 t, %1; cvt.u32.u64 %0, t; }" : "=r"(a) : "l"(p));
    return a;
}
__device__ __forceinline__ void mma16816(float* c,
                                         uint32_t a0, uint32_t a1, uint32_t a2, uint32_t a3,
                                         uint32_t b0, uint32_t b1) {
    asm volatile(
        "mma.sync.aligned.m16n8k16.row.col.f32.bf16.bf16.f32 "
        "{%0,%1,%2,%3}, {%4,%5,%6,%7}, {%8,%9}, {%0,%1,%2,%3};"
        : "+f"(c[0]), "+f"(c[1]), "+f"(c[2]), "+f"(c[3])
        : "r"(a0), "r"(a1), "r"(a2), "r"(a3), "r"(b0), "r"(b1));
}
__device__ __forceinline__ void ldsm_x4(uint32_t& r0, uint32_t& r1, uint32_t& r2, uint32_t& r3,
                                        uint32_t addr) {
    asm volatile("ldmatrix.sync.aligned.m8n8.x4.shared.b16 {%0,%1,%2,%3}, [%4];"
                 : "=r"(r0), "=r"(r1), "=r"(r2), "=r"(r3) : "r"(addr));
}
__device__ __forceinline__ uint32_t pack2(float a, float b) {
    __nv_bfloat162 t = __floats2bfloat162_rn(a, b);
    return *(uint32_t*)&t;
}

// ---------------- W split: B[n][k] = W[k][n], bf16 hi/lo ----------------
__global__ __launch_bounds__(256) void wsplit_kernel(const float* __restrict__ W) {
    int e = blockIdx.x * blockDim.x + threadIdx.x;
    if (e >= D * D) return;
    int n = e >> 7, k = e & 127;
    float w = W[k * D + n];
    __nv_bfloat16 hi = __float2bfloat16_rn(w);
    g_Whi[n * D + k] = hi;
    g_Wlo[n * D + k] = __float2bfloat16_rn(w - __bfloat162float(hi));
}

// ---------------- fused count+fill into padded buckets ----------------
__global__ __launch_bounds__(256) void fill_kernel(const int* __restrict__ edge_src,
                                                   const int* __restrict__ edge_dst) {
    int t = blockIdx.x * blockDim.x + threadIdx.x;
    if (t < E_CNT / 4) {
        int4 s = ((const int4*)edge_src)[t];
        int4 d = ((const int4*)edge_dst)[t];
        int p0 = atomicAdd(&g_deg[d.x], 1);
        int p1 = atomicAdd(&g_deg[d.y], 1);
        int p2 = atomicAdd(&g_deg[d.z], 1);
        int p3 = atomicAdd(&g_deg[d.w], 1);
        if (p0 < BKT) g_edges[(size_t)d.x * BKT + p0] = s.x;
        if (p1 < BKT) g_edges[(size_t)d.y * BKT + p1] = s.y;
        if (p2 < BKT) g_edges[(size_t)d.z * BKT + p2] = s.z;
        if (p3 < BKT) g_edges[(size_t)d.w * BKT + p3] = s.w;
    }
}

// ---------------- fused agg + GEMM: out = relu(mean(H[nbrs]) @ W + flag*b) ----
// smem: bias @0 (512), flags @512 (512), A_hi @1024, A_lo, B_hi, B_lo
#define SM_BIAS  0
#define SM_FLAG  512
#define SM_AHI   1024
#define SM_ALO   (SM_AHI + TILE_M * LDA * 2)
#define SM_BHI   (SM_ALO + TILE_M * LDA * 2)
#define SM_BLO   (SM_BHI + TILE_M * LDA * 2)
#define SM_TOTAL (SM_BLO + TILE_M * LDA * 2)       // 1024 + 4*34816 = 140288

__global__ __launch_bounds__(256, 1) void fused_kernel(const float* __restrict__ H,
                                                       const float* __restrict__ b,
                                                       float* __restrict__ out) {
    extern __shared__ char smem[];
    const int tid = threadIdx.x;
    const int wid = tid >> 5, lane = tid & 31;
    const int block_row = blockIdx.x * TILE_M;

    __nv_bfloat16* sAhi = (__nv_bfloat16*)(smem + SM_AHI);
    __nv_bfloat16* sAlo = (__nv_bfloat16*)(smem + SM_ALO);
    __nv_bfloat16* sBhi = (__nv_bfloat16*)(smem + SM_BHI);
    __nv_bfloat16* sBlo = (__nv_bfloat16*)(smem + SM_BLO);
    float* sbias = (float*)(smem + SM_BIAS);
    float* sflag = (float*)(smem + SM_FLAG);

    // ---- load B tiles (16B chunks, padded rows) ----
    for (int i = tid; i < D * 16; i += 256) {
        int n = i >> 4, q = i & 15;
        *(uint4*)&sBhi[n * LDA + q * 8] = *(const uint4*)&g_Whi[n * D + q * 8];
        *(uint4*)&sBlo[n * LDA + q * 8] = *(const uint4*)&g_Wlo[n * D + q * 8];
    }
    if (tid < D) sbias[tid] = b[tid];

    // ---- aggregation phase: warp w aggregates dst rows [w*16, w*16+16) ----
    {
        const float4* H4 = (const float4*)H;
        for (int j = 0; j < 16; j++) {
            int r = wid * 16 + j;
            int grow = block_row + r;
            float4 acc = make_float4(0.f, 0.f, 0.f, 0.f);
            int deg = 0;
            if (grow < N_DST) {
                deg = g_deg[grow];
                const int* bucket = &g_edges[(size_t)grow * BKT];
                int cnt = min(deg, BKT);
                int i = 0;
                for (; i + 7 < cnt; i += 8) {
                    float4 v[8];
#pragma unroll
                    for (int q = 0; q < 8; q++)
                        v[q] = H4[(size_t)bucket[i + q] * 32 + lane];
#pragma unroll
                    for (int q = 0; q < 8; q++) {
                        acc.x += v[q].x; acc.y += v[q].y;
                        acc.z += v[q].z; acc.w += v[q].w;
                    }
                }
                if (i + 3 < cnt) {
                    float4 v[4];
#pragma unroll
                    for (int q = 0; q < 4; q++)
                        v[q] = H4[(size_t)bucket[i + q] * 32 + lane];
#pragma unroll
                    for (int q = 0; q < 4; q++) {
                        acc.x += v[q].x; acc.y += v[q].y;
                        acc.z += v[q].z; acc.w += v[q].w;
                    }
                    i += 4;
                }
                for (; i < cnt; i++) {
                    float4 a = H4[(size_t)bucket[i] * 32 + lane];
                    acc.x += a.x; acc.y += a.y; acc.z += a.z; acc.w += a.w;
                }
            }
            float inv = 1.0f / fmaxf((float)deg, 1.0f);
            acc.x *= inv; acc.y *= inv; acc.z *= inv; acc.w *= inv;

            __nv_bfloat16 h0 = __float2bfloat16_rn(acc.x);
            __nv_bfloat16 h1 = __float2bfloat16_rn(acc.y);
            __nv_bfloat16 h2 = __float2bfloat16_rn(acc.z);
            __nv_bfloat16 h3 = __float2bfloat16_rn(acc.w);
            uint2 hv, lv;
            { __nv_bfloat162 t0; t0.x = h0; t0.y = h1; hv.x = *(uint32_t*)&t0;
              __nv_bfloat162 t1; t1.x = h2; t1.y = h3; hv.y = *(uint32_t*)&t1; }
            lv.x = pack2(acc.x - __bfloat162float(h0), acc.y - __bfloat162float(h1));
            lv.y = pack2(acc.z - __bfloat162float(h2), acc.w - __bfloat162float(h3));

            // row r, cols [lane*4, lane*4+4) -> byte offset r*LDA*2 + lane*8
            *(uint2*)&sAhi[r * LDA + lane * 4] = hv;
            *(uint2*)&sAlo[r * LDA + lane * 4] = lv;
            if (lane == 0) sflag[r] = (deg > 0) ? 1.0f : 0.0f;
        }
    }
    __syncthreads();

    // ---- MMA phase ----
    const int wr = wid & 3, wc = wid >> 2;
    const int m0 = wr * 32, n0 = wc * 64;
    const int rit = lane & 7;
    const int g   = lane >> 3;
    const int og  = lane >> 2;
    const int tg  = lane & 3;

    const uint32_t sb = smem_u32(smem);
    const uint32_t aoff = (uint32_t)((m0 + rit + ((g & 1) << 3)) * LDA + ((g >> 1) << 3)) * 2;
    uint32_t boff[4];
#pragma unroll
    for (int p = 0; p < 4; p++)
        boff[p] = (uint32_t)((n0 + p * 16 + rit + ((g >> 1) << 3)) * LDA + ((g & 1) << 3)) * 2;

    float acc[2][8][4];
#pragma unroll
    for (int mt = 0; mt < 2; mt++)
#pragma unroll
        for (int nt = 0; nt < 8; nt++)
#pragma unroll
            for (int q = 0; q < 4; q++) acc[mt][nt][q] = 0.f;

#pragma unroll
    for (int pass = 0; pass < 3; pass++) {
        const uint32_t aBase = sb + ((pass == 2) ? SM_ALO : SM_AHI) + aoff;
        const uint32_t bBase = sb + ((pass == 1) ? SM_BLO : SM_BHI);
#pragma unroll
        for (int ks = 0; ks < 8; ks++) {
            const uint32_t kb = ks * 32;
            uint32_t a0[4], a1[4];
            ldsm_x4(a0[0], a0[1], a0[2], a0[3], aBase + kb);
            ldsm_x4(a1[0], a1[1], a1[2], a1[3], aBase + 16 * LDA * 2 + kb);
#pragma unroll
            for (int p = 0; p < 4; p++) {
                uint32_t r0, r1, r2, r3;
                ldsm_x4(r0, r1, r2, r3, bBase + boff[p] + kb);
                mma16816(acc[0][2 * p    ], a0[0], a0[1], a0[2], a0[3], r0, r1);
                mma16816(acc[1][2 * p    ], a1[0], a1[1], a1[2], a1[3], r0, r1);
                mma16816(acc[0][2 * p + 1], a0[0], a0[1], a0[2], a0[3], r2, r3);
                mma16816(acc[1][2 * p + 1], a1[0], a1[1], a1[2], a1[3], r2, r3);
            }
        }
    }

    // ---- epilogue: bias*flag + relu ----
#pragma unroll
    for (int mt = 0; mt < 2; mt++) {
        const int r  = m0 + mt * 16 + og;
        const int gA = block_row + r;
        const int gB = gA + 8;
        float fA = sflag[r];
        float fB = sflag[r + 8];
#pragma unroll
        for (int nt = 0; nt < 8; nt++) {
            const int c = n0 + nt * 8 + tg * 2;
            float bx = sbias[c], by = sbias[c + 1];
            if (gA < N_DST) {
                float2 v;
                v.x = fmaxf(acc[mt][nt][0] + bx * fA, 0.f);
                v.y = fmaxf(acc[mt][nt][1] + by * fA, 0.f);
                *(float2*)&out[(size_t)gA * D + c] = v;
            }
            if (gB < N_DST) {
                float2 v;
                v.x = fmaxf(acc[mt][nt][2] + bx * fB, 0.f);
                v.y = fmaxf(acc[mt][nt][3] + by * fB, 0.f);
                *(float2*)&out[(size_t)gB * D + c] = v;
            }
        }
    }
}

// ---------------- launch (single stream, 4 nodes) ----------------
extern "C" void kernel_launch(void* const* d_in, const int* in_sizes, int n_in,
                              void* d_out, int out_size) {
    const float* H_src    = (const float*)d_in[0];
    const float* W        = (const float*)d_in[1];
    const float* b        = (const float*)d_in[2];
    const int*   edge_src = (const int*)d_in[3];
    const int*   edge_dst = (const int*)d_in[4];
    float* out = (float*)d_out;

    static void* d_deg = nullptr;
    if (!d_deg) {   // one-time setup on the uncaptured correctness call
        cudaFuncSetAttribute(fused_kernel,
                             cudaFuncAttributeMaxDynamicSharedMemorySize, SM_TOTAL);
        cudaGetSymbolAddress(&d_deg, g_deg);
    }

    cudaMemsetAsync(d_deg, 0, N_DST * sizeof(int), 0);
    wsplit_kernel<<<WSP_NB, 256>>>(W);
    fill_kernel<<<FILL_NB, 256>>>(edge_src, edge_dst);
    fused_kernel<<<GRID_N, 256, SM_TOTAL>>>(H_src, b, out);
}

// round 15
// speedup vs baseline: 1.6204x; 1.6204x over previous
#include <cuda_runtime.h>
#include <cuda_bf16.h>
#include <cuda_fp16.h>
#include <cstdint>

#define N_SRC  100000
#define N_DST  50000
#define E_CNT  600000
#define D      128          // D_IN == D_OUT == 128

#define BKT    64           // bucket capacity per dst (Poisson(12): P(deg>64) ~ 1e-38)

#define FILL_NB  ((E_CNT / 4 + 255) / 256)                   // 586
#define WSP_NB   ((D * D + 255) / 256)                       // 64
#define HPREP_NB ((N_SRC * D / 8) / 256)                     // 6250

#define TILE_M 128
#define GRID_N ((N_DST + TILE_M - 1) / TILE_M)               // 391

// padded row stride for smem tiles (bf16 elements)
#define LDA 136

// ---------------- device scratch (no allocation allowed) ----------------
__device__ int   g_deg[N_DST];
__device__ int   g_edges[(size_t)N_DST * BKT];   // 12.8 MB padded buckets
__device__ __half g_Hh[(size_t)N_SRC * D];       // 25.6 MB fp16 H
// W split into bf16 hi/lo, stored as B[n][k] (= W[k][n]) row-major, k contiguous
__device__ __nv_bfloat16 g_Whi[D * D];
__device__ __nv_bfloat16 g_Wlo[D * D];
// aggregated means, split bf16 hi/lo, row-major [N_DST][D]
__device__ __nv_bfloat16 g_Ahi[(size_t)N_DST * D];
__device__ __nv_bfloat16 g_Alo[(size_t)N_DST * D];
__device__ float g_bflag[N_DST];

// ---------------- helpers ----------------
__device__ __forceinline__ uint32_t smem_u32(const void* p) {
    uint32_t a;
    asm("{ .reg .u64 t; cvta.to.shared.u64 t, %1; cvt.u32.u64 %0, t; }" : "=r"(a) : "l"(p));
    return a;
}
__device__ __forceinline__ void mma16816(float* c,
                                         uint32_t a0, uint32_t a1, uint32_t a2, uint32_t a3,
                                         uint32_t b0, uint32_t b1) {
    asm volatile(
        "mma.sync.aligned.m16n8k16.row.col.f32.bf16.bf16.f32 "
        "{%0,%1,%2,%3}, {%4,%5,%6,%7}, {%8,%9}, {%0,%1,%2,%3};"
        : "+f"(c[0]), "+f"(c[1]), "+f"(c[2]), "+f"(c[3])
        : "r"(a0), "r"(a1), "r"(a2), "r"(a3), "r"(b0), "r"(b1));
}
__device__ __forceinline__ void ldsm_x4(uint32_t& r0, uint32_t& r1, uint32_t& r2, uint32_t& r3,
                                        uint32_t addr) {
    asm volatile("ldmatrix.sync.aligned.m8n8.x4.shared.b16 {%0,%1,%2,%3}, [%4];"
                 : "=r"(r0), "=r"(r1), "=r"(r2), "=r"(r3) : "r"(addr));
}
__device__ __forceinline__ uint32_t pack2(float a, float b) {
    __nv_bfloat162 t = __floats2bfloat162_rn(a, b);
    return *(uint32_t*)&t;
}

// ------- fused: count+fill buckets | W split | H->fp16, one grid -------------
__global__ __launch_bounds__(256) void fill_wsplit_hprep_kernel(
        const int* __restrict__ edge_src, const int* __restrict__ edge_dst,
        const float* __restrict__ W, const float* __restrict__ H) {
    int blk = blockIdx.x;
    if (blk < FILL_NB) {
        int t = blk * 256 + threadIdx.x;
        if (t < E_CNT / 4) {
            int4 s = ((const int4*)edge_src)[t];
            int4 d = ((const int4*)edge_dst)[t];
            int p0 = atomicAdd(&g_deg[d.x], 1);
            int p1 = atomicAdd(&g_deg[d.y], 1);
            int p2 = atomicAdd(&g_deg[d.z], 1);
            int p3 = atomicAdd(&g_deg[d.w], 1);
            if (p0 < BKT) g_edges[(size_t)d.x * BKT + p0] = s.x;
            if (p1 < BKT) g_edges[(size_t)d.y * BKT + p1] = s.y;
            if (p2 < BKT) g_edges[(size_t)d.z * BKT + p2] = s.z;
            if (p3 < BKT) g_edges[(size_t)d.w * BKT + p3] = s.w;
        }
    } else if (blk < FILL_NB + WSP_NB) {
        int e = (blk - FILL_NB) * 256 + threadIdx.x;
        if (e < D * D) {
            int n = e >> 7, k = e & 127;
            float w = W[k * D + n];
            __nv_bfloat16 hi = __float2bfloat16_rn(w);
            g_Whi[n * D + k] = hi;
            g_Wlo[n * D + k] = __float2bfloat16_rn(w - __bfloat162float(hi));
        }
    } else {
        size_t t = (size_t)(blk - FILL_NB - WSP_NB) * 256 + threadIdx.x;  // one per 8 floats
        if (t < (size_t)N_SRC * D / 8) {
            const float4* H4 = (const float4*)H;
            float4 a = H4[t * 2], c = H4[t * 2 + 1];
            uint4 o;
            { __half2 h = __floats2half2_rn(a.x, a.y); o.x = *(uint32_t*)&h; }
            { __half2 h = __floats2half2_rn(a.z, a.w); o.y = *(uint32_t*)&h; }
            { __half2 h = __floats2half2_rn(c.x, c.y); o.z = *(uint32_t*)&h; }
            { __half2 h = __floats2half2_rn(c.z, c.w); o.w = *(uint32_t*)&h; }
            ((uint4*)g_Hh)[t] = o;
        }
    }
}

// ---------------- aggregation: one warp per dst, fp16 gather (uint2/lane) ----
__global__ __launch_bounds__(256) void aggH_kernel() {
    int warp = (blockIdx.x * blockDim.x + threadIdx.x) >> 5;
    int lane = threadIdx.x & 31;
    if (warp >= N_DST) return;

    int deg  = g_deg[warp];
    int cnt  = min(deg, BKT);
    const int* bucket = &g_edges[(size_t)warp * BKT];

    const uint2* H2 = (const uint2*)g_Hh;      // 4 halves per lane
    float4 acc = make_float4(0.f, 0.f, 0.f, 0.f);

    int i = 0;
    for (; i + 7 < cnt; i += 8) {
        uint2 v[8];
#pragma unroll
        for (int q = 0; q < 8; q++)
            v[q] = H2[(size_t)bucket[i + q] * 32 + lane];
#pragma unroll
        for (int q = 0; q < 8; q++) {
            float2 f0 = __half22float2(*(__half2*)&v[q].x);
            float2 f1 = __half22float2(*(__half2*)&v[q].y);
            acc.x += f0.x; acc.y += f0.y; acc.z += f1.x; acc.w += f1.y;
        }
    }
    if (i + 3 < cnt) {
        uint2 v[4];
#pragma unroll
        for (int q = 0; q < 4; q++)
            v[q] = H2[(size_t)bucket[i + q] * 32 + lane];
#pragma unroll
        for (int q = 0; q < 4; q++) {
            float2 f0 = __half22float2(*(__half2*)&v[q].x);
            float2 f1 = __half22float2(*(__half2*)&v[q].y);
            acc.x += f0.x; acc.y += f0.y; acc.z += f1.x; acc.w += f1.y;
        }
        i += 4;
    }
    for (; i < cnt; i++) {
        uint2 v = H2[(size_t)bucket[i] * 32 + lane];
        float2 f0 = __half22float2(*(__half2*)&v.x);
        float2 f1 = __half22float2(*(__half2*)&v.y);
        acc.x += f0.x; acc.y += f0.y; acc.z += f1.x; acc.w += f1.y;
    }

    float inv = 1.0f / fmaxf((float)deg, 1.0f);
    acc.x *= inv; acc.y *= inv; acc.z *= inv; acc.w *= inv;

    __nv_bfloat16 h0 = __float2bfloat16_rn(acc.x);
    __nv_bfloat16 h1 = __float2bfloat16_rn(acc.y);
    __nv_bfloat16 h2 = __float2bfloat16_rn(acc.z);
    __nv_bfloat16 h3 = __float2bfloat16_rn(acc.w);
    uint2 hv, lv;
    { __nv_bfloat162 t0; t0.x = h0; t0.y = h1; hv.x = *(uint32_t*)&t0;
      __nv_bfloat162 t1; t1.x = h2; t1.y = h3; hv.y = *(uint32_t*)&t1; }
    lv.x = pack2(acc.x - __bfloat162float(h0), acc.y - __bfloat162float(h1));
    lv.y = pack2(acc.z - __bfloat162float(h2), acc.w - __bfloat162float(h3));

    ((uint2*)g_Ahi)[(size_t)warp * 32 + lane] = hv;
    ((uint2*)g_Alo)[(size_t)warp * 32 + lane] = lv;
    if (lane == 0) g_bflag[warp] = (deg > 0) ? 1.0f : 0.0f;
}

// ---------------- GEMM: out = relu(aggH @ W + flag*b), split-bf16 + ldmatrix --
#define SM_BIAS  0
#define SM_AHI   512
#define SM_ALO   (SM_AHI + TILE_M * LDA * 2)
#define SM_BHI   (SM_ALO + TILE_M * LDA * 2)
#define SM_BLO   (SM_BHI + TILE_M * LDA * 2)
#define SM_TOTAL (SM_BLO + TILE_M * LDA * 2)       // 512 + 4*34816 = 139776

__global__ __launch_bounds__(256, 1) void gemm_tc_kernel(const float* __restrict__ b,
                                                         float* __restrict__ out) {
    extern __shared__ char smem[];
    const int tid = threadIdx.x;
    const int wid = tid >> 5, lane = tid & 31;
    const int block_row = blockIdx.x * TILE_M;

    __nv_bfloat16* sAhi = (__nv_bfloat16*)(smem + SM_AHI);
    __nv_bfloat16* sAlo = (__nv_bfloat16*)(smem + SM_ALO);
    __nv_bfloat16* sBhi = (__nv_bfloat16*)(smem + SM_BHI);
    __nv_bfloat16* sBlo = (__nv_bfloat16*)(smem + SM_BLO);
    float* sbias = (float*)(smem + SM_BIAS);

    for (int i = tid; i < D * 16; i += 256) {
        int n = i >> 4, q = i & 15;
        *(uint4*)&sBhi[n * LDA + q * 8] = *(const uint4*)&g_Whi[n * D + q * 8];
        *(uint4*)&sBlo[n * LDA + q * 8] = *(const uint4*)&g_Wlo[n * D + q * 8];
    }
    if (tid < D) sbias[tid] = b[tid];

    {
        const uint4 z = make_uint4(0u, 0u, 0u, 0u);
        for (int i = tid; i < TILE_M * 16; i += 256) {
            int r = i >> 4, q = i & 15;
            int grow = block_row + r;
            uint4 hv = z, lv = z;
            if (grow < N_DST) {
                hv = *(const uint4*)&g_Ahi[(size_t)grow * D + q * 8];
                lv = *(const uint4*)&g_Alo[(size_t)grow * D + q * 8];
            }
            *(uint4*)&sAhi[r * LDA + q * 8] = hv;
            *(uint4*)&sAlo[r * LDA + q * 8] = lv;
        }
    }
    __syncthreads();

    const int wr = wid & 3, wc = wid >> 2;
    const int m0 = wr * 32, n0 = wc * 64;
    const int rit = lane & 7;
    const int g   = lane >> 3;
    const int og  = lane >> 2;
    const int tg  = lane & 3;

    const uint32_t sb = smem_u32(smem);
    const uint32_t aoff = (uint32_t)((m0 + rit + ((g & 1) << 3)) * LDA + ((g >> 1) << 3)) * 2;
    uint32_t boff[4];
#pragma unroll
    for (int p = 0; p < 4; p++)
        boff[p] = (uint32_t)((n0 + p * 16 + rit + ((g >> 1) << 3)) * LDA + ((g & 1) << 3)) * 2;

    float acc[2][8][4];
#pragma unroll
    for (int mt = 0; mt < 2; mt++)
#pragma unroll
        for (int nt = 0; nt < 8; nt++)
#pragma unroll
            for (int q = 0; q < 4; q++) acc[mt][nt][q] = 0.f;

#pragma unroll
    for (int pass = 0; pass < 3; pass++) {
        const uint32_t aBase = sb + ((pass == 2) ? SM_ALO : SM_AHI) + aoff;
        const uint32_t bBase = sb + ((pass == 1) ? SM_BLO : SM_BHI);
#pragma unroll
        for (int ks = 0; ks < 8; ks++) {
            const uint32_t kb = ks * 32;
            uint32_t a0[4], a1[4];
            ldsm_x4(a0[0], a0[1], a0[2], a0[3], aBase + kb);
            ldsm_x4(a1[0], a1[1], a1[2], a1[3], aBase + 16 * LDA * 2 + kb);
#pragma unroll
            for (int p = 0; p < 4; p++) {
                uint32_t r0, r1, r2, r3;
                ldsm_x4(r0, r1, r2, r3, bBase + boff[p] + kb);
                mma16816(acc[0][2 * p    ], a0[0], a0[1], a0[2], a0[3], r0, r1);
                mma16816(acc[1][2 * p    ], a1[0], a1[1], a1[2], a1[3], r0, r1);
                mma16816(acc[0][2 * p + 1], a0[0], a0[1], a0[2], a0[3], r2, r3);
                mma16816(acc[1][2 * p + 1], a1[0], a1[1], a1[2], a1[3], r2, r3);
            }
        }
    }

#pragma unroll
    for (int mt = 0; mt < 2; mt++) {
        const int r  = m0 + mt * 16 + og;
        const int gA = block_row + r;
        const int gB = gA + 8;
        float fA = (gA < N_DST) ? g_bflag[gA] : 0.f;
        float fB = (gB < N_DST) ? g_bflag[gB] : 0.f;
#pragma unroll
        for (int nt = 0; nt < 8; nt++) {
            const int c = n0 + nt * 8 + tg * 2;
            float bx = sbias[c], by = sbias[c + 1];
            if (gA < N_DST) {
                float2 v;
                v.x = fmaxf(acc[mt][nt][0] + bx * fA, 0.f);
                v.y = fmaxf(acc[mt][nt][1] + by * fA, 0.f);
                *(float2*)&out[(size_t)gA * D + c] = v;
            }
            if (gB < N_DST) {
                float2 v;
                v.x = fmaxf(acc[mt][nt][2] + bx * fB, 0.f);
                v.y = fmaxf(acc[mt][nt][3] + by * fB, 0.f);
                *(float2*)&out[(size_t)gB * D + c] = v;
            }
        }
    }
}

// ---------------- launch (single stream, 4 nodes) ----------------
extern "C" void kernel_launch(void* const* d_in, const int* in_sizes, int n_in,
                              void* d_out, int out_size) {
    const float* H_src    = (const float*)d_in[0];
    const float* W        = (const float*)d_in[1];
    const float* b        = (const float*)d_in[2];
    const int*   edge_src = (const int*)d_in[3];
    const int*   edge_dst = (const int*)d_in[4];
    float* out = (float*)d_out;

    static void* d_deg = nullptr;
    if (!d_deg) {   // one-time setup on the uncaptured correctness call
        cudaFuncSetAttribute(gemm_tc_kernel,
                             cudaFuncAttributeMaxDynamicSharedMemorySize, SM_TOTAL);
        cudaGetSymbolAddress(&d_deg, g_deg);
    }

    cudaMemsetAsync(d_deg, 0, N_DST * sizeof(int), 0);
    fill_wsplit_hprep_kernel<<<FILL_NB + WSP_NB + HPREP_NB, 256>>>(edge_src, edge_dst, W, H_src);
    aggH_kernel<<<(N_DST * 32 + 255) / 256, 256>>>();
    gemm_tc_kernel<<<GRID_N, 256, SM_TOTAL>>>(b, out);
}

// round 16
// speedup vs baseline: 1.6567x; 1.0224x over previous
#include <cuda_runtime.h>
#include <cuda_bf16.h>
#include <cuda_fp16.h>
#include <cstdint>

#define N_SRC  100000
#define N_DST  50000
#define E_CNT  600000
#define D      128          // D_IN == D_OUT == 128

#define BKT    64           // bucket capacity per dst (Poisson(12): P(deg>64) ~ 1e-38)

#define FILL_NB  ((E_CNT / 4 + 255) / 256)                   // 586
#define WSP_NB   ((D * D + 255) / 256)                       // 64
#define HPREP_NB ((N_SRC * D / 8) / 256)                     // 6250

#define TILE_M 128
#define GRID_N ((N_DST + TILE_M - 1) / TILE_M)               // 391
#define HALF1_NB 196                                         // rows [0, 25088)
#define HALF_ROWS (HALF1_NB * TILE_M)                        // 25088
#define HALF2_NB (GRID_N - HALF1_NB)                         // 195

// padded row stride for smem tiles (bf16 elements)
#define LDA 136

// ---------------- device scratch (no allocation allowed) ----------------
__device__ int   g_deg[N_DST];
__device__ int   g_edges[(size_t)N_DST * BKT];   // 12.8 MB padded buckets
__device__ __half g_Hh[(size_t)N_SRC * D];       // 25.6 MB fp16 H
// W split into bf16 hi/lo, stored as B[n][k] (= W[k][n]) row-major, k contiguous
__device__ __nv_bfloat16 g_Whi[D * D];
__device__ __nv_bfloat16 g_Wlo[D * D];
// aggregated means, split bf16 hi/lo, row-major [N_DST][D]
__device__ __nv_bfloat16 g_Ahi[(size_t)N_DST * D];
__device__ __nv_bfloat16 g_Alo[(size_t)N_DST * D];
__device__ float g_bflag[N_DST];

// ---------------- helpers ----------------
__device__ __forceinline__ uint32_t smem_u32(const void* p) {
    uint32_t a;
    asm("{ .reg .u64 t; cvta.to.shared.u64 t, %1; cvt.u32.u64 %0, t; }" : "=r"(a) : "l"(p));
    return a;
}
__device__ __forceinline__ void mma16816(float* c,
                                         uint32_t a0, uint32_t a1, uint32_t a2, uint32_t a3,
                                         uint32_t b0, uint32_t b1) {
    asm volatile(
        "mma.sync.aligned.m16n8k16.row.col.f32.bf16.bf16.f32 "
        "{%0,%1,%2,%3}, {%4,%5,%6,%7}, {%8,%9}, {%0,%1,%2,%3};"
        : "+f"(c[0]), "+f"(c[1]), "+f"(c[2]), "+f"(c[3])
        : "r"(a0), "r"(a1), "r"(a2), "r"(a3), "r"(b0), "r"(b1));
}
__device__ __forceinline__ void ldsm_x4(uint32_t& r0, uint32_t& r1, uint32_t& r2, uint32_t& r3,
                                        uint32_t addr) {
    asm volatile("ldmatrix.sync.aligned.m8n8.x4.shared.b16 {%0,%1,%2,%3}, [%4];"
                 : "=r"(r0), "=r"(r1), "=r"(r2), "=r"(r3) : "r"(addr));
}
__device__ __forceinline__ uint32_t pack2(float a, float b) {
    __nv_bfloat162 t = __floats2bfloat162_rn(a, b);
    return *(uint32_t*)&t;
}

// ------- fused: count+fill buckets | W split | H->fp16, one grid -------------
__global__ __launch_bounds__(256) void fill_wsplit_hprep_kernel(
        const int* __restrict__ edge_src, const int* __restrict__ edge_dst,
        const float* __restrict__ W, const float* __restrict__ H) {
    int blk = blockIdx.x;
    if (blk < FILL_NB) {
        int t = blk * 256 + threadIdx.x;
        if (t < E_CNT / 4) {
            int4 s = ((const int4*)edge_src)[t];
            int4 d = ((const int4*)edge_dst)[t];
            int p0 = atomicAdd(&g_deg[d.x], 1);
            int p1 = atomicAdd(&g_deg[d.y], 1);
            int p2 = atomicAdd(&g_deg[d.z], 1);
            int p3 = atomicAdd(&g_deg[d.w], 1);
            if (p0 < BKT) g_edges[(size_t)d.x * BKT + p0] = s.x;
            if (p1 < BKT) g_edges[(size_t)d.y * BKT + p1] = s.y;
            if (p2 < BKT) g_edges[(size_t)d.z * BKT + p2] = s.z;
            if (p3 < BKT) g_edges[(size_t)d.w * BKT + p3] = s.w;
        }
    } else if (blk < FILL_NB + WSP_NB) {
        int e = (blk - FILL_NB) * 256 + threadIdx.x;
        if (e < D * D) {
            int n = e >> 7, k = e & 127;
            float w = W[k * D + n];
            __nv_bfloat16 hi = __float2bfloat16_rn(w);
            g_Whi[n * D + k] = hi;
            g_Wlo[n * D + k] = __float2bfloat16_rn(w - __bfloat162float(hi));
        }
    } else {
        size_t t = (size_t)(blk - FILL_NB - WSP_NB) * 256 + threadIdx.x;  // one per 8 floats
        if (t < (size_t)N_SRC * D / 8) {
            const float4* H4 = (const float4*)H;
            float4 a = H4[t * 2], c = H4[t * 2 + 1];
            uint4 o;
            { __half2 h = __floats2half2_rn(a.x, a.y); o.x = *(uint32_t*)&h; }
            { __half2 h = __floats2half2_rn(a.z, a.w); o.y = *(uint32_t*)&h; }
            { __half2 h = __floats2half2_rn(c.x, c.y); o.z = *(uint32_t*)&h; }
            { __half2 h = __floats2half2_rn(c.z, c.w); o.w = *(uint32_t*)&h; }
            ((uint4*)g_Hh)[t] = o;
        }
    }
}

// ---------------- aggregation over dst range [dst0, dst1) ----------------
__global__ __launch_bounds__(256) void aggH_kernel(int dst0, int dst1) {
    int warp = dst0 + ((blockIdx.x * blockDim.x + threadIdx.x) >> 5);
    int lane = threadIdx.x & 31;
    if (warp >= dst1) return;

    int deg  = g_deg[warp];
    int cnt  = min(deg, BKT);
    const int* bucket = &g_edges[(size_t)warp * BKT];

    const uint2* H2 = (const uint2*)g_Hh;      // 4 halves per lane
    float4 acc = make_float4(0.f, 0.f, 0.f, 0.f);

    int i = 0;
    for (; i + 7 < cnt; i += 8) {
        uint2 v[8];
#pragma unroll
        for (int q = 0; q < 8; q++)
            v[q] = H2[(size_t)bucket[i + q] * 32 + lane];
#pragma unroll
        for (int q = 0; q < 8; q++) {
            float2 f0 = __half22float2(*(__half2*)&v[q].x);
            float2 f1 = __half22float2(*(__half2*)&v[q].y);
            acc.x += f0.x; acc.y += f0.y; acc.z += f1.x; acc.w += f1.y;
        }
    }
    if (i + 3 < cnt) {
        uint2 v[4];
#pragma unroll
        for (int q = 0; q < 4; q++)
            v[q] = H2[(size_t)bucket[i + q] * 32 + lane];
#pragma unroll
        for (int q = 0; q < 4; q++) {
            float2 f0 = __half22float2(*(__half2*)&v[q].x);
            float2 f1 = __half22float2(*(__half2*)&v[q].y);
            acc.x += f0.x; acc.y += f0.y; acc.z += f1.x; acc.w += f1.y;
        }
        i += 4;
    }
    for (; i < cnt; i++) {
        uint2 v = H2[(size_t)bucket[i] * 32 + lane];
        float2 f0 = __half22float2(*(__half2*)&v.x);
        float2 f1 = __half22float2(*(__half2*)&v.y);
        acc.x += f0.x; acc.y += f0.y; acc.z += f1.x; acc.w += f1.y;
    }

    float inv = 1.0f / fmaxf((float)deg, 1.0f);
    acc.x *= inv; acc.y *= inv; acc.z *= inv; acc.w *= inv;

    __nv_bfloat16 h0 = __float2bfloat16_rn(acc.x);
    __nv_bfloat16 h1 = __float2bfloat16_rn(acc.y);
    __nv_bfloat16 h2 = __float2bfloat16_rn(acc.z);
    __nv_bfloat16 h3 = __float2bfloat16_rn(acc.w);
    uint2 hv, lv;
    { __nv_bfloat162 t0; t0.x = h0; t0.y = h1; hv.x = *(uint32_t*)&t0;
      __nv_bfloat162 t1; t1.x = h2; t1.y = h3; hv.y = *(uint32_t*)&t1; }
    lv.x = pack2(acc.x - __bfloat162float(h0), acc.y - __bfloat162float(h1));
    lv.y = pack2(acc.z - __bfloat162float(h2), acc.w - __bfloat162float(h3));

    ((uint2*)g_Ahi)[(size_t)warp * 32 + lane] = hv;
    ((uint2*)g_Alo)[(size_t)warp * 32 + lane] = lv;
    if (lane == 0) g_bflag[warp] = (deg > 0) ? 1.0f : 0.0f;
}

// ---------------- GEMM over row range starting at row_base --------------------
#define SM_BIAS  0
#define SM_AHI   512
#define SM_ALO   (SM_AHI + TILE_M * LDA * 2)
#define SM_BHI   (SM_ALO + TILE_M * LDA * 2)
#define SM_BLO   (SM_BHI + TILE_M * LDA * 2)
#define SM_TOTAL (SM_BLO + TILE_M * LDA * 2)       // 512 + 4*34816 = 139776

__global__ __launch_bounds__(256, 1) void gemm_tc_kernel(const float* __restrict__ b,
                                                         float* __restrict__ out,
                                                         int row_base) {
    extern __shared__ char smem[];
    const int tid = threadIdx.x;
    const int wid = tid >> 5, lane = tid & 31;
    const int block_row = row_base + blockIdx.x * TILE_M;

    __nv_bfloat16* sAhi = (__nv_bfloat16*)(smem + SM_AHI);
    __nv_bfloat16* sAlo = (__nv_bfloat16*)(smem + SM_ALO);
    __nv_bfloat16* sBhi = (__nv_bfloat16*)(smem + SM_BHI);
    __nv_bfloat16* sBlo = (__nv_bfloat16*)(smem + SM_BLO);
    float* sbias = (float*)(smem + SM_BIAS);

    for (int i = tid; i < D * 16; i += 256) {
        int n = i >> 4, q = i & 15;
        *(uint4*)&sBhi[n * LDA + q * 8] = *(const uint4*)&g_Whi[n * D + q * 8];
        *(uint4*)&sBlo[n * LDA + q * 8] = *(const uint4*)&g_Wlo[n * D + q * 8];
    }
    if (tid < D) sbias[tid] = b[tid];

    {
        const uint4 z = make_uint4(0u, 0u, 0u, 0u);
        for (int i = tid; i < TILE_M * 16; i += 256) {
            int r = i >> 4, q = i & 15;
            int grow = block_row + r;
            uint4 hv = z, lv = z;
            if (grow < N_DST) {
                hv = *(const uint4*)&g_Ahi[(size_t)grow * D + q * 8];
                lv = *(const uint4*)&g_Alo[(size_t)grow * D + q * 8];
            }
            *(uint4*)&sAhi[r * LDA + q * 8] = hv;
            *(uint4*)&sAlo[r * LDA + q * 8] = lv;
        }
    }
    __syncthreads();

    const int wr = wid & 3, wc = wid >> 2;
    const int m0 = wr * 32, n0 = wc * 64;
    const int rit = lane & 7;
    const int g   = lane >> 3;
    const int og  = lane >> 2;
    const int tg  = lane & 3;

    const uint32_t sb = smem_u32(smem);
    const uint32_t aoff = (uint32_t)((m0 + rit + ((g & 1) << 3)) * LDA + ((g >> 1) << 3)) * 2;
    uint32_t boff[4];
#pragma unroll
    for (int p = 0; p < 4; p++)
        boff[p] = (uint32_t)((n0 + p * 16 + rit + ((g >> 1) << 3)) * LDA + ((g & 1) << 3)) * 2;

    float acc[2][8][4];
#pragma unroll
    for (int mt = 0; mt < 2; mt++)
#pragma unroll
        for (int nt = 0; nt < 8; nt++)
#pragma unroll
            for (int q = 0; q < 4; q++) acc[mt][nt][q] = 0.f;

#pragma unroll
    for (int pass = 0; pass < 3; pass++) {
        const uint32_t aBase = sb + ((pass == 2) ? SM_ALO : SM_AHI) + aoff;
        const uint32_t bBase = sb + ((pass == 1) ? SM_BLO : SM_BHI);
#pragma unroll
        for (int ks = 0; ks < 8; ks++) {
            const uint32_t kb = ks * 32;
            uint32_t a0[4], a1[4];
            ldsm_x4(a0[0], a0[1], a0[2], a0[3], aBase + kb);
            ldsm_x4(a1[0], a1[1], a1[2], a1[3], aBase + 16 * LDA * 2 + kb);
#pragma unroll
            for (int p = 0; p < 4; p++) {
                uint32_t r0, r1, r2, r3;
                ldsm_x4(r0, r1, r2, r3, bBase + boff[p] + kb);
                mma16816(acc[0][2 * p    ], a0[0], a0[1], a0[2], a0[3], r0, r1);
                mma16816(acc[1][2 * p    ], a1[0], a1[1], a1[2], a1[3], r0, r1);
                mma16816(acc[0][2 * p + 1], a0[0], a0[1], a0[2], a0[3], r2, r3);
                mma16816(acc[1][2 * p + 1], a1[0], a1[1], a1[2], a1[3], r2, r3);
            }
        }
    }

#pragma unroll
    for (int mt = 0; mt < 2; mt++) {
        const int r  = m0 + mt * 16 + og;
        const int gA = block_row + r;
        const int gB = gA + 8;
        float fA = (gA < N_DST) ? g_bflag[gA] : 0.f;
        float fB = (gB < N_DST) ? g_bflag[gB] : 0.f;
#pragma unroll
        for (int nt = 0; nt < 8; nt++) {
            const int c = n0 + nt * 8 + tg * 2;
            float bx = sbias[c], by = sbias[c + 1];
            if (gA < N_DST) {
                float2 v;
                v.x = fmaxf(acc[mt][nt][0] + bx * fA, 0.f);
                v.y = fmaxf(acc[mt][nt][1] + by * fA, 0.f);
                *(float2*)&out[(size_t)gA * D + c] = v;
            }
            if (gB < N_DST) {
                float2 v;
                v.x = fmaxf(acc[mt][nt][2] + bx * fB, 0.f);
                v.y = fmaxf(acc[mt][nt][3] + by * fB, 0.f);
                *(float2*)&out[(size_t)gB * D + c] = v;
            }
        }
    }
}

// ---------------- launch: fork agg/gemm halves across two streams ------------
extern "C" void kernel_launch(void* const* d_in, const int* in_sizes, int n_in,
                              void* d_out, int out_size) {
    const float* H_src    = (const float*)d_in[0];
    const float* W        = (const float*)d_in[1];
    const float* b        = (const float*)d_in[2];
    const int*   edge_src = (const int*)d_in[3];
    const int*   edge_dst = (const int*)d_in[4];
    float* out = (float*)d_out;

    static void* d_deg = nullptr;
    static cudaStream_t s1 = nullptr;
    static cudaEvent_t evFork = nullptr, evJoin = nullptr;
    if (!d_deg) {   // one-time setup on the uncaptured correctness call
        cudaFuncSetAttribute(gemm_tc_kernel,
                             cudaFuncAttributeMaxDynamicSharedMemorySize, SM_TOTAL);
        cudaGetSymbolAddress(&d_deg, g_deg);
        cudaStreamCreateWithFlags(&s1, cudaStreamNonBlocking);
        cudaEventCreateWithFlags(&evFork, cudaEventDisableTiming);
        cudaEventCreateWithFlags(&evJoin, cudaEventDisableTiming);
    }

    cudaMemsetAsync(d_deg, 0, N_DST * sizeof(int), 0);                       // #0
    fill_wsplit_hprep_kernel<<<FILL_NB + WSP_NB + HPREP_NB, 256>>>(          // #1
        edge_src, edge_dst, W, H_src);

    // fork after fill (both halves depend on complete buckets)
    cudaEventRecord(evFork, 0);
    cudaStreamWaitEvent(s1, evFork, 0);

    aggH_kernel<<<(HALF_ROWS * 32 + 255) / 256, 256>>>(0, HALF_ROWS);        // #2 (s0)
    aggH_kernel<<<((N_DST - HALF_ROWS) * 32 + 255) / 256, 256, 0, s1>>>(     // #3 (s1)
        HALF_ROWS, N_DST);
    gemm_tc_kernel<<<HALF1_NB, 256, SM_TOTAL>>>(b, out, 0);                  // #4 (s0)
    gemm_tc_kernel<<<HALF2_NB, 256, SM_TOTAL, s1>>>(b, out, HALF_ROWS);      // #5 (s1) -> profiled

    // join: main stream completion must cover s1's work
    cudaEventRecord(evJoin, s1);
    cudaStreamWaitEvent(0, evJoin, 0);
}

// round 17
// speedup vs baseline: 1.7038x; 1.0284x over previous
#include <cuda_runtime.h>
#include <cuda_bf16.h>
#include <cuda_fp16.h>
#include <cstdint>

#define N_SRC  100000
#define N_DST  50000
#define E_CNT  600000
#define D      128          // D_IN == D_OUT == 128

#define BKT    64           // bucket capacity per dst (Poisson(12): P(deg>64) ~ 1e-38)

#define FILL_NB  ((E_CNT / 4 + 255) / 256)                   // 586
#define WSP_NB   ((D * D + 255) / 256)                       // 64
#define HPREP_NB ((N_SRC * D / 8) / 256)                     // 6250

#define TILE_M 128
#define GRID_N ((N_DST + TILE_M - 1) / TILE_M)               // 391
#define HALF1_NB 196                                         // rows [0, 25088)
#define HALF_ROWS (HALF1_NB * TILE_M)                        // 25088
#define HALF2_NB (GRID_N - HALF1_NB)                         // 195

// padded row stride for smem tiles (bf16 elements)
#define LDA 136

// ---------------- device scratch (no allocation allowed) ----------------
__device__ int   g_deg[N_DST];
__device__ int   g_edges[(size_t)N_DST * BKT];   // 12.8 MB padded buckets
__device__ __half g_Hh[(size_t)N_SRC * D];       // 25.6 MB fp16 H
// W split into bf16 hi/lo, stored as B[n][k] (= W[k][n]) row-major, k contiguous
__device__ __nv_bfloat16 g_Whi[D * D];
__device__ __nv_bfloat16 g_Wlo[D * D];
// aggregated means, split bf16 hi/lo, row-major [N_DST][D]
__device__ __nv_bfloat16 g_Ahi[(size_t)N_DST * D];
__device__ __nv_bfloat16 g_Alo[(size_t)N_DST * D];
__device__ float g_bflag[N_DST];

// ---------------- helpers ----------------
__device__ __forceinline__ uint32_t smem_u32(const void* p) {
    uint32_t a;
    asm("{ .reg .u64 t; cvta.to.shared.u64 t, %1; cvt.u32.u64 %0, t; }" : "=r"(a) : "l"(p));
    return a;
}
__device__ __forceinline__ void mma16816(float* c,
                                         uint32_t a0, uint32_t a1, uint32_t a2, uint32_t a3,
                                         uint32_t b0, uint32_t b1) {
    asm volatile(
        "mma.sync.aligned.m16n8k16.row.col.f32.bf16.bf16.f32 "
        "{%0,%1,%2,%3}, {%4,%5,%6,%7}, {%8,%9}, {%0,%1,%2,%3};"
        : "+f"(c[0]), "+f"(c[1]), "+f"(c[2]), "+f"(c[3])
        : "r"(a0), "r"(a1), "r"(a2), "r"(a3), "r"(b0), "r"(b1));
}
__device__ __forceinline__ void ldsm_x4(uint32_t& r0, uint32_t& r1, uint32_t& r2, uint32_t& r3,
                                        uint32_t addr) {
    asm volatile("ldmatrix.sync.aligned.m8n8.x4.shared.b16 {%0,%1,%2,%3}, [%4];"
                 : "=r"(r0), "=r"(r1), "=r"(r2), "=r"(r3) : "r"(addr));
}
__device__ __forceinline__ uint32_t pack2(float a, float b) {
    __nv_bfloat162 t = __floats2bfloat162_rn(a, b);
    return *(uint32_t*)&t;
}

// ------- fused: count+fill buckets | W split | H->fp16, one grid -------------
__global__ __launch_bounds__(256) void fill_wsplit_hprep_kernel(
        const int* __restrict__ edge_src, const int* __restrict__ edge_dst,
        const float* __restrict__ W, const float* __restrict__ H) {
    int blk = blockIdx.x;
    if (blk < FILL_NB) {
        int t = blk * 256 + threadIdx.x;
        if (t < E_CNT / 4) {
            int4 s = ((const int4*)edge_src)[t];
            int4 d = ((const int4*)edge_dst)[t];
            int p0 = atomicAdd(&g_deg[d.x], 1);
            int p1 = atomicAdd(&g_deg[d.y], 1);
            int p2 = atomicAdd(&g_deg[d.z], 1);
            int p3 = atomicAdd(&g_deg[d.w], 1);
            if (p0 < BKT) g_edges[(size_t)d.x * BKT + p0] = s.x;
            if (p1 < BKT) g_edges[(size_t)d.y * BKT + p1] = s.y;
            if (p2 < BKT) g_edges[(size_t)d.z * BKT + p2] = s.z;
            if (p3 < BKT) g_edges[(size_t)d.w * BKT + p3] = s.w;
        }
    } else if (blk < FILL_NB + WSP_NB) {
        int e = (blk - FILL_NB) * 256 + threadIdx.x;
        if (e < D * D) {
            int n = e >> 7, k = e & 127;
            float w = W[k * D + n];
            __nv_bfloat16 hi = __float2bfloat16_rn(w);
            g_Whi[n * D + k] = hi;
            g_Wlo[n * D + k] = __float2bfloat16_rn(w - __bfloat162float(hi));
        }
    } else {
        size_t t = (size_t)(blk - FILL_NB - WSP_NB) * 256 + threadIdx.x;  // one per 8 floats
        if (t < (size_t)N_SRC * D / 8) {
            const float4* H4 = (const float4*)H;
            float4 a = H4[t * 2], c = H4[t * 2 + 1];
            uint4 o;
            { __half2 h = __floats2half2_rn(a.x, a.y); o.x = *(uint32_t*)&h; }
            { __half2 h = __floats2half2_rn(a.z, a.w); o.y = *(uint32_t*)&h; }
            { __half2 h = __floats2half2_rn(c.x, c.y); o.z = *(uint32_t*)&h; }
            { __half2 h = __floats2half2_rn(c.z, c.w); o.w = *(uint32_t*)&h; }
            ((uint4*)g_Hh)[t] = o;
        }
    }
}

// ---------------- aggregation over dst range [dst0, dst1) ----------------
__global__ __launch_bounds__(256) void aggH_kernel(int dst0, int dst1) {
    int warp = dst0 + ((blockIdx.x * blockDim.x + threadIdx.x) >> 5);
    int lane = threadIdx.x & 31;
    if (warp >= dst1) return;

    int deg  = g_deg[warp];
    int cnt  = min(deg, BKT);
    const int* bucket = &g_edges[(size_t)warp * BKT];

    const uint2* H2 = (const uint2*)g_Hh;      // 4 halves per lane
    float4 acc = make_float4(0.f, 0.f, 0.f, 0.f);

    int i = 0;
    for (; i + 7 < cnt; i += 8) {
        uint2 v[8];
#pragma unroll
        for (int q = 0; q < 8; q++)
            v[q] = H2[(size_t)bucket[i + q] * 32 + lane];
#pragma unroll
        for (int q = 0; q < 8; q++) {
            float2 f0 = __half22float2(*(__half2*)&v[q].x);
            float2 f1 = __half22float2(*(__half2*)&v[q].y);
            acc.x += f0.x; acc.y += f0.y; acc.z += f1.x; acc.w += f1.y;
        }
    }
    if (i + 3 < cnt) {
        uint2 v[4];
#pragma unroll
        for (int q = 0; q < 4; q++)
            v[q] = H2[(size_t)bucket[i + q] * 32 + lane];
#pragma unroll
        for (int q = 0; q < 4; q++) {
            float2 f0 = __half22float2(*(__half2*)&v[q].x);
            float2 f1 = __half22float2(*(__half2*)&v[q].y);
            acc.x += f0.x; acc.y += f0.y; acc.z += f1.x; acc.w += f1.y;
        }
        i += 4;
    }
    for (; i < cnt; i++) {
        uint2 v = H2[(size_t)bucket[i] * 32 + lane];
        float2 f0 = __half22float2(*(__half2*)&v.x);
        float2 f1 = __half22float2(*(__half2*)&v.y);
        acc.x += f0.x; acc.y += f0.y; acc.z += f1.x; acc.w += f1.y;
    }

    float inv = 1.0f / fmaxf((float)deg, 1.0f);
    acc.x *= inv; acc.y *= inv; acc.z *= inv; acc.w *= inv;

    __nv_bfloat16 h0 = __float2bfloat16_rn(acc.x);
    __nv_bfloat16 h1 = __float2bfloat16_rn(acc.y);
    __nv_bfloat16 h2 = __float2bfloat16_rn(acc.z);
    __nv_bfloat16 h3 = __float2bfloat16_rn(acc.w);
    uint2 hv, lv;
    { __nv_bfloat162 t0; t0.x = h0; t0.y = h1; hv.x = *(uint32_t*)&t0;
      __nv_bfloat162 t1; t1.x = h2; t1.y = h3; hv.y = *(uint32_t*)&t1; }
    lv.x = pack2(acc.x - __bfloat162float(h0), acc.y - __bfloat162float(h1));
    lv.y = pack2(acc.z - __bfloat162float(h2), acc.w - __bfloat162float(h3));

    ((uint2*)g_Ahi)[(size_t)warp * 32 + lane] = hv;
    ((uint2*)g_Alo)[(size_t)warp * 32 + lane] = lv;
    if (lane == 0) g_bflag[warp] = (deg > 0) ? 1.0f : 0.0f;
}

// ---------------- GEMM (512 threads, 16 warps, 32x32 warp tiles) -------------
#define SM_BIAS  0
#define SM_AHI   512
#define SM_ALO   (SM_AHI + TILE_M * LDA * 2)
#define SM_BHI   (SM_ALO + TILE_M * LDA * 2)
#define SM_BLO   (SM_BHI + TILE_M * LDA * 2)
#define SM_TOTAL (SM_BLO + TILE_M * LDA * 2)       // 512 + 4*34816 = 139776

__global__ __launch_bounds__(512, 1) void gemm_tc_kernel(const float* __restrict__ b,
                                                         float* __restrict__ out,
                                                         int row_base) {
    extern __shared__ char smem[];
    const int tid = threadIdx.x;
    const int wid = tid >> 5, lane = tid & 31;
    const int block_row = row_base + blockIdx.x * TILE_M;

    __nv_bfloat16* sAhi = (__nv_bfloat16*)(smem + SM_AHI);
    __nv_bfloat16* sAlo = (__nv_bfloat16*)(smem + SM_ALO);
    __nv_bfloat16* sBhi = (__nv_bfloat16*)(smem + SM_BHI);
    __nv_bfloat16* sBlo = (__nv_bfloat16*)(smem + SM_BLO);
    float* sbias = (float*)(smem + SM_BIAS);

    for (int i = tid; i < D * 16; i += 512) {
        int n = i >> 4, q = i & 15;
        *(uint4*)&sBhi[n * LDA + q * 8] = *(const uint4*)&g_Whi[n * D + q * 8];
        *(uint4*)&sBlo[n * LDA + q * 8] = *(const uint4*)&g_Wlo[n * D + q * 8];
    }
    if (tid < D) sbias[tid] = b[tid];

    {
        const uint4 z = make_uint4(0u, 0u, 0u, 0u);
        for (int i = tid; i < TILE_M * 16; i += 512) {
            int r = i >> 4, q = i & 15;
            int grow = block_row + r;
            uint4 hv = z, lv = z;
            if (grow < N_DST) {
                hv = *(const uint4*)&g_Ahi[(size_t)grow * D + q * 8];
                lv = *(const uint4*)&g_Alo[(size_t)grow * D + q * 8];
            }
            *(uint4*)&sAhi[r * LDA + q * 8] = hv;
            *(uint4*)&sAlo[r * LDA + q * 8] = lv;
        }
    }
    __syncthreads();

    // 16 warps: wr = wid&3 -> m0, wc = wid>>2 -> n0; each warp 32x32 output
    const int wr = wid & 3, wc = wid >> 2;
    const int m0 = wr * 32, n0 = wc * 32;
    const int rit = lane & 7;
    const int g   = lane >> 3;
    const int og  = lane >> 2;
    const int tg  = lane & 3;

    const uint32_t sb = smem_u32(smem);
    const uint32_t aoff = (uint32_t)((m0 + rit + ((g & 1) << 3)) * LDA + ((g >> 1) << 3)) * 2;
    uint32_t boff[2];
#pragma unroll
    for (int p = 0; p < 2; p++)
        boff[p] = (uint32_t)((n0 + p * 16 + rit + ((g >> 1) << 3)) * LDA + ((g & 1) << 3)) * 2;

    float acc[2][4][4];
#pragma unroll
    for (int mt = 0; mt < 2; mt++)
#pragma unroll
        for (int nt = 0; nt < 4; nt++)
#pragma unroll
            for (int q = 0; q < 4; q++) acc[mt][nt][q] = 0.f;

#pragma unroll
    for (int pass = 0; pass < 3; pass++) {
        const uint32_t aBase = sb + ((pass == 2) ? SM_ALO : SM_AHI) + aoff;
        const uint32_t bBase = sb + ((pass == 1) ? SM_BLO : SM_BHI);
#pragma unroll
        for (int ks = 0; ks < 8; ks++) {
            const uint32_t kb = ks * 32;
            uint32_t a0[4], a1[4];
            ldsm_x4(a0[0], a0[1], a0[2], a0[3], aBase + kb);
            ldsm_x4(a1[0], a1[1], a1[2], a1[3], aBase + 16 * LDA * 2 + kb);
#pragma unroll
            for (int p = 0; p < 2; p++) {
                uint32_t r0, r1, r2, r3;
                ldsm_x4(r0, r1, r2, r3, bBase + boff[p] + kb);
                mma16816(acc[0][2 * p    ], a0[0], a0[1], a0[2], a0[3], r0, r1);
                mma16816(acc[1][2 * p    ], a1[0], a1[1], a1[2], a1[3], r0, r1);
                mma16816(acc[0][2 * p + 1], a0[0], a0[1], a0[2], a0[3], r2, r3);
                mma16816(acc[1][2 * p + 1], a1[0], a1[1], a1[2], a1[3], r2, r3);
            }
        }
    }

#pragma unroll
    for (int mt = 0; mt < 2; mt++) {
        const int r  = m0 + mt * 16 + og;
        const int gA = block_row + r;
        const int gB = gA + 8;
        float fA = (gA < N_DST) ? g_bflag[gA] : 0.f;
        float fB = (gB < N_DST) ? g_bflag[gB] : 0.f;
#pragma unroll
        for (int nt = 0; nt < 4; nt++) {
            const int c = n0 + nt * 8 + tg * 2;
            float bx = sbias[c], by = sbias[c + 1];
            if (gA < N_DST) {
                float2 v;
                v.x = fmaxf(acc[mt][nt][0] + bx * fA, 0.f);
                v.y = fmaxf(acc[mt][nt][1] + by * fA, 0.f);
                *(float2*)&out[(size_t)gA * D + c] = v;
            }
            if (gB < N_DST) {
                float2 v;
                v.x = fmaxf(acc[mt][nt][2] + bx * fB, 0.f);
                v.y = fmaxf(acc[mt][nt][3] + by * fB, 0.f);
                *(float2*)&out[(size_t)gB * D + c] = v;
            }
        }
    }
}

// ---------------- launch: fork agg/gemm halves across two streams ------------
extern "C" void kernel_launch(void* const* d_in, const int* in_sizes, int n_in,
                              void* d_out, int out_size) {
    const float* H_src    = (const float*)d_in[0];
    const float* W        = (const float*)d_in[1];
    const float* b        = (const float*)d_in[2];
    const int*   edge_src = (const int*)d_in[3];
    const int*   edge_dst = (const int*)d_in[4];
    float* out = (float*)d_out;

    static void* d_deg = nullptr;
    static cudaStream_t s1 = nullptr;
    static cudaEvent_t evFork = nullptr, evJoin = nullptr;
    if (!d_deg) {   // one-time setup on the uncaptured correctness call
        cudaFuncSetAttribute(gemm_tc_kernel,
                             cudaFuncAttributeMaxDynamicSharedMemorySize, SM_TOTAL);
        cudaGetSymbolAddress(&d_deg, g_deg);
        cudaStreamCreateWithFlags(&s1, cudaStreamNonBlocking);
        cudaEventCreateWithFlags(&evFork, cudaEventDisableTiming);
        cudaEventCreateWithFlags(&evJoin, cudaEventDisableTiming);
    }

    cudaMemsetAsync(d_deg, 0, N_DST * sizeof(int), 0);                       // #0
    fill_wsplit_hprep_kernel<<<FILL_NB + WSP_NB + HPREP_NB, 256>>>(          // #1
        edge_src, edge_dst, W, H_src);

    // fork after fill (both halves depend on complete buckets)
    cudaEventRecord(evFork, 0);
    cudaStreamWaitEvent(s1, evFork, 0);

    aggH_kernel<<<(HALF_ROWS * 32 + 255) / 256, 256>>>(0, HALF_ROWS);        // #2 (s0)
    aggH_kernel<<<((N_DST - HALF_ROWS) * 32 + 255) / 256, 256, 0, s1>>>(     // #3 (s1)
        HALF_ROWS, N_DST);
    gemm_tc_kernel<<<HALF1_NB, 512, SM_TOTAL>>>(b, out, 0);                  // #4 (s0)
    gemm_tc_kernel<<<HALF2_NB, 512, SM_TOTAL, s1>>>(b, out, HALF_ROWS);      // #5 (s1) -> profiled

    // join: main stream completion must cover s1's work
    cudaEventRecord(evJoin, s1);
    cudaStreamWaitEvent(0, evJoin, 0);
}